// round 15
// baseline (speedup 1.0000x reference)
#include <cuda_runtime.h>
#include <math.h>

constexpr int C  = 128;
constexpr int S  = 24;
constexpr int NV = S * S * S;      // 13824
constexpr int KW = 3;
constexpr int NW = KW * KW * KW;   // 27

__device__ float g_q[NV * C];
__device__ float g_k[NV * C];
__device__ float g_v[NV * C];
__device__ float g_bias[NW];
__device__ float g_wt[3 * C * C];  // transposed weights: [mat][c][o]

typedef unsigned long long u64;

// ---- packed f32x2 helpers (Blackwell FFMA2 path, PTX-only) -----------------
__device__ __forceinline__ u64 pk2(float lo, float hi) {
    u64 d;
    asm("mov.b64 %0, {%1, %2};" : "=l"(d) : "f"(lo), "f"(hi));
    return d;
}
__device__ __forceinline__ void fma2(u64& c, u64 a, u64 b) {
    asm("fma.rn.f32x2 %0, %1, %2, %0;" : "+l"(c) : "l"(a), "l"(b));
}
__device__ __forceinline__ float2 up2(u64 d) {
    float2 r;
    asm("mov.b64 {%0, %1}, %2;" : "=f"(r.x), "=f"(r.y) : "l"(d));
    return r;
}

// ---------------------------------------------------------------------------
// Prep: bias table. 288 threads, one warp per partial sum.
// ---------------------------------------------------------------------------
__global__ void prep_kernel(const float* __restrict__ rh,
                            const float* __restrict__ rw,
                            const float* __restrict__ rd) {
    __shared__ float a[9];
    int w = threadIdx.x >> 5, lane = threadIdx.x & 31;
    if (w < 9) {
        const float* p = (w < 3) ? rh : (w < 6 ? rw : rd);
        int k = w % 3;
        float s = 0.f;
        for (int c = lane; c < 64; c += 32) s += p[c * 3 + k];
#pragma unroll
        for (int o = 16; o; o >>= 1) s += __shfl_xor_sync(0xffffffffu, s, o);
        if (lane == 0) a[w] = s;
    }
    __syncthreads();
    int t = threadIdx.x;
    if (t < NW)
        g_bias[t] = a[t / 9] + a[3 + (t / 3) % 3] + a[6 + t % 3];
}

// ---------------------------------------------------------------------------
// Weight transpose: g_wt[mat][c][o] = w[mat][o][c].  grid (4,4,3), block (32,8)
// ---------------------------------------------------------------------------
__global__ void wt_kernel(const float* __restrict__ w0,
                          const float* __restrict__ w1,
                          const float* __restrict__ w2) {
    __shared__ float t[32][33];
    int mat = blockIdx.z;
    const float* w = (mat == 0) ? w0 : (mat == 1 ? w1 : w2);
    int o0 = blockIdx.y * 32, c0 = blockIdx.x * 32;
    int tx = threadIdx.x;
    for (int i = threadIdx.y; i < 32; i += 8)
        t[i][tx] = w[(o0 + i) * C + c0 + tx];
    __syncthreads();
    float* dst = g_wt + mat * C * C;
    for (int i = threadIdx.y; i < 32; i += 8)
        dst[(c0 + i) * C + o0 + tx] = t[tx][i];
}

// ---------------------------------------------------------------------------
// GEMM: out[v][o] = sum_c wt[c][o] * x[c][v] + b[o]
// Block tile 128 voxels x 128 channels, 256 threads.
// Register tile 8 voxels x 8 channels, computed as 8 x 4 packed f32x2 pairs
// (channel pairs), using fma.rn.f32x2 for 2x fp32 FMA throughput.
// ---------------------------------------------------------------------------
__global__ void __launch_bounds__(256, 2)
gemm_kernel(const float* __restrict__ x,
            const float* __restrict__ b0,
            const float* __restrict__ b1,
            const float* __restrict__ b2) {
    __shared__ float xs[16][128];
    __shared__ float ws[16][128];

    int mat = blockIdx.y;
    const float* wt   = g_wt + mat * C * C;
    const float* bias = (mat == 0) ? b0 : (mat == 1 ? b1 : b2);
    float* out = (mat == 0) ? g_q : (mat == 1 ? g_k : g_v);

    int tid = threadIdx.x;
    int tx = tid & 15, ty = tid >> 4;
    int v0 = blockIdx.x * 128;
    int ob = tx * 8;   // output-channel base
    int vb = ty * 8;   // voxel base

    int lc = tid >> 4;
    int lv = (tid & 15) * 8;

    u64 acc[8][4];
#pragma unroll
    for (int i = 0; i < 8; i++)
#pragma unroll
        for (int j = 0; j < 4; j++) acc[i][j] = 0ull;  // two packed +0.0f

    float4 px0, px1, pw0, pw1;
    {
        const float* xp = x + lc * NV + v0 + lv;
        px0 = *(const float4*)xp;
        px1 = *(const float4*)(xp + 4);
        const float* wp = wt + lc * C + lv;
        pw0 = *(const float4*)wp;
        pw1 = *(const float4*)(wp + 4);
    }

    for (int ch = 0; ch < 8; ch++) {
        __syncthreads();
        *(float4*)&xs[lc][lv]     = px0;
        *(float4*)&xs[lc][lv + 4] = px1;
        *(float4*)&ws[lc][lv]     = pw0;
        *(float4*)&ws[lc][lv + 4] = pw1;
        __syncthreads();

        if (ch < 7) {
            int c0 = (ch + 1) * 16;
            const float* xp = x + (c0 + lc) * NV + v0 + lv;
            px0 = *(const float4*)xp;
            px1 = *(const float4*)(xp + 4);
            const float* wp = wt + (c0 + lc) * C + lv;
            pw0 = *(const float4*)wp;
            pw1 = *(const float4*)(wp + 4);
        }

#pragma unroll 4
        for (int k = 0; k < 16; k++) {
            float4 xv0 = *(const float4*)&xs[k][vb];
            float4 xv1 = *(const float4*)&xs[k][vb + 4];
            float4 wv0 = *(const float4*)&ws[k][ob];
            float4 wv1 = *(const float4*)&ws[k][ob + 4];
            u64 wp2[4];
            wp2[0] = pk2(wv0.x, wv0.y);
            wp2[1] = pk2(wv0.z, wv0.w);
            wp2[2] = pk2(wv1.x, wv1.y);
            wp2[3] = pk2(wv1.z, wv1.w);
            float xr[8] = {xv0.x, xv0.y, xv0.z, xv0.w,
                           xv1.x, xv1.y, xv1.z, xv1.w};
#pragma unroll
            for (int i = 0; i < 8; i++) {
                u64 xb = pk2(xr[i], xr[i]);
#pragma unroll
                for (int j = 0; j < 4; j++)
                    fma2(acc[i][j], xb, wp2[j]);
            }
        }
    }

    float4 bb0 = *(const float4*)(bias + ob);
    float4 bb1 = *(const float4*)(bias + ob + 4);
#pragma unroll
    for (int i = 0; i < 8; i++) {
        float2 a0 = up2(acc[i][0]);
        float2 a1 = up2(acc[i][1]);
        float2 a2 = up2(acc[i][2]);
        float2 a3 = up2(acc[i][3]);
        float* orow = out + (v0 + vb + i) * C + ob;
        float4 s0, s1;
        s0.x = a0.x + bb0.x; s0.y = a0.y + bb0.y;
        s0.z = a1.x + bb0.z; s0.w = a1.y + bb0.w;
        s1.x = a2.x + bb1.x; s1.y = a2.y + bb1.y;
        s1.z = a3.x + bb1.z; s1.w = a3.y + bb1.w;
        *(float4*)orow       = s0;
        *(float4*)(orow + 4) = s1;
    }
}

// ---------------------------------------------------------------------------
// Attention: one WARP per voxel. 256 threads = 8 warps = one 2x2x2 voxel cube
// per block (L1 locality for shared K/V neighbor rows). Softmax fully
// in-warp (27 <= 32 lanes): no __syncthreads, no smem staging.
// ---------------------------------------------------------------------------
__global__ void __launch_bounds__(256)
attn_kernel(const float* __restrict__ bk,
            const float* __restrict__ bv,
            float* __restrict__ out) {
    const unsigned FULL = 0xffffffffu;
    int lane = threadIdx.x & 31;
    int wrp  = threadIdx.x >> 5;

    // block -> 2x2x2 tile of voxels; warp -> voxel within tile
    int t = blockIdx.x;                 // 0 .. 12^3-1
    int tH = t / 144;
    int rr = t - tH * 144;
    int tW = rr / 12;
    int tD = rr - tW * 12;
    int h = tH * 2 + ((wrp >> 2) & 1);
    int w = tW * 2 + ((wrp >> 1) & 1);
    int d = tD * 2 + (wrp & 1);
    int v = (h * S + w) * S + d;

    // q: 4 channels per lane
    const float4 qv = *(const float4*)(g_q + v * C + lane * 4);

    // qsum over all 128 channels
    float qs = qv.x + qv.y + qv.z + qv.w;
#pragma unroll
    for (int o = 16; o; o >>= 1) qs += __shfl_xor_sync(FULL, qs, o);

    // neighbor index for lane s (< 27), else -1
    int ni = -1;
    float bias = 0.f;
    if (lane < NW) {
        int i = lane / 9, j = (lane / 3) % 3, l = lane % 3;
        int hh = h + i - 1, ww = w + j - 1, dd = d + l - 1;
        bool ok = (unsigned)hh < (unsigned)S && (unsigned)ww < (unsigned)S &&
                  (unsigned)dd < (unsigned)S;
        ni = ok ? ((hh * S + ww) * S + dd) : -1;
        bias = g_bias[lane];
    }

    // QK: 27 dot products; lane s keeps logit_s
    float logit = 0.f;
#pragma unroll
    for (int s = 0; s < NW; s++) {
        int ns = __shfl_sync(FULL, ni, s);
        const float* kp = (ns >= 0) ? (g_k + (size_t)ns * C) : bk;
        float4 kv = *(const float4*)(kp + lane * 4);
        float p = qv.x * kv.x;
        p = fmaf(qv.y, kv.y, p);
        p = fmaf(qv.z, kv.z, p);
        p = fmaf(qv.w, kv.w, p);
#pragma unroll
        for (int o = 16; o; o >>= 1) p += __shfl_xor_sync(FULL, p, o);
        if (lane == s) logit = p;
    }

    // softmax over 27, entirely in-warp
    float li = (lane < NW) ? fmaf(qs, bias, logit) : -INFINITY;
    float m = li;
#pragma unroll
    for (int o = 16; o; o >>= 1) m = fmaxf(m, __shfl_xor_sync(FULL, m, o));
    float p = (lane < NW) ? __expf(li - m) : 0.f;
    float ssum = p;
#pragma unroll
    for (int o = 16; o; o >>= 1) ssum += __shfl_xor_sync(FULL, ssum, o);
    float prob = p / ssum;

    // AV: weighted sum of 27 V rows, 4 channels per lane
    float4 acc = make_float4(0.f, 0.f, 0.f, 0.f);
#pragma unroll
    for (int s = 0; s < NW; s++) {
        int ns   = __shfl_sync(FULL, ni, s);
        float ps = __shfl_sync(FULL, prob, s);
        const float* vp = (ns >= 0) ? (g_v + (size_t)ns * C) : bv;
        float4 vv = *(const float4*)(vp + lane * 4);
        acc.x = fmaf(ps, vv.x, acc.x);
        acc.y = fmaf(ps, vv.y, acc.y);
        acc.z = fmaf(ps, vv.z, acc.z);
        acc.w = fmaf(ps, vv.w, acc.w);
    }
    *(float4*)(out + v * C + lane * 4) = acc;
}

// ---------------------------------------------------------------------------
// Launch.  Inputs: x, wq, bq, wk, bk, wv, bv, rel_h, rel_w, rel_d
// ---------------------------------------------------------------------------
extern "C" void kernel_launch(void* const* d_in, const int* in_sizes, int n_in,
                              void* d_out, int out_size) {
    const float* x   = (const float*)d_in[0];
    const float* wq  = (const float*)d_in[1];
    const float* bq  = (const float*)d_in[2];
    const float* wk  = (const float*)d_in[3];
    const float* bk  = (const float*)d_in[4];
    const float* wv  = (const float*)d_in[5];
    const float* bv  = (const float*)d_in[6];
    const float* rh  = (const float*)d_in[7];
    const float* rw  = (const float*)d_in[8];
    const float* rd  = (const float*)d_in[9];
    float* out = (float*)d_out;

    prep_kernel<<<1, 288>>>(rh, rw, rd);

    dim3 tgrid(4, 4, 3);
    wt_kernel<<<tgrid, dim3(32, 8)>>>(wq, wk, wv);

    dim3 ggrid(NV / 128, 3);
    gemm_kernel<<<ggrid, 256>>>(x, bq, bk, bv);

    attn_kernel<<<(S / 2) * (S / 2) * (S / 2), 256>>>(bk, bv, out);
}

// round 16
// speedup vs baseline: 1.1698x; 1.1698x over previous
#include <cuda_runtime.h>
#include <math.h>

constexpr int C  = 128;
constexpr int S  = 24;
constexpr int NV = S * S * S;      // 13824
constexpr int KW = 3;
constexpr int NW = KW * KW * KW;   // 27

__device__ float g_q[NV * C];
__device__ float g_k[NV * C];
__device__ float g_v[NV * C];
__device__ float g_bias[NW];
__device__ float g_wt[3 * C * C];  // transposed weights: [mat][c][o]

typedef unsigned long long u64;

// ---- packed f32x2 helpers (Blackwell FFMA2 path, PTX-only) -----------------
__device__ __forceinline__ u64 pk2(float lo, float hi) {
    u64 d;
    asm("mov.b64 %0, {%1, %2};" : "=l"(d) : "f"(lo), "f"(hi));
    return d;
}
__device__ __forceinline__ void fma2(u64& c, u64 a, u64 b) {
    asm("fma.rn.f32x2 %0, %1, %2, %0;" : "+l"(c) : "l"(a), "l"(b));
}
__device__ __forceinline__ float2 up2(u64 d) {
    float2 r;
    asm("mov.b64 {%0, %1}, %2;" : "=f"(r.x), "=f"(r.y) : "l"(d));
    return r;
}

// ---- cp.async helpers ------------------------------------------------------
__device__ __forceinline__ void cpa16(void* s, const void* g) {
    unsigned sa = (unsigned)__cvta_generic_to_shared(s);
    asm volatile("cp.async.cg.shared.global [%0], [%1], 16;" :: "r"(sa), "l"(g) : "memory");
}
__device__ __forceinline__ void cpcommit() {
    asm volatile("cp.async.commit_group;" ::: "memory");
}
__device__ __forceinline__ void cpwait0() {
    asm volatile("cp.async.wait_group 0;" ::: "memory");
}

// ---------------------------------------------------------------------------
// Prep: bias table. 288 threads, one warp per partial sum.
// ---------------------------------------------------------------------------
__global__ void prep_kernel(const float* __restrict__ rh,
                            const float* __restrict__ rw,
                            const float* __restrict__ rd) {
    __shared__ float a[9];
    int w = threadIdx.x >> 5, lane = threadIdx.x & 31;
    if (w < 9) {
        const float* p = (w < 3) ? rh : (w < 6 ? rw : rd);
        int k = w % 3;
        float s = 0.f;
        for (int c = lane; c < 64; c += 32) s += p[c * 3 + k];
#pragma unroll
        for (int o = 16; o; o >>= 1) s += __shfl_xor_sync(0xffffffffu, s, o);
        if (lane == 0) a[w] = s;
    }
    __syncthreads();
    int t = threadIdx.x;
    if (t < NW)
        g_bias[t] = a[t / 9] + a[3 + (t / 3) % 3] + a[6 + t % 3];
}

// ---------------------------------------------------------------------------
// Weight transpose: g_wt[mat][c][o] = w[mat][o][c].  grid (4,4,3), block (32,8)
// ---------------------------------------------------------------------------
__global__ void wt_kernel(const float* __restrict__ w0,
                          const float* __restrict__ w1,
                          const float* __restrict__ w2) {
    __shared__ float t[32][33];
    int mat = blockIdx.z;
    const float* w = (mat == 0) ? w0 : (mat == 1 ? w1 : w2);
    int o0 = blockIdx.y * 32, c0 = blockIdx.x * 32;
    int tx = threadIdx.x;
    for (int i = threadIdx.y; i < 32; i += 8)
        t[i][tx] = w[(o0 + i) * C + c0 + tx];
    __syncthreads();
    float* dst = g_wt + mat * C * C;
    for (int i = threadIdx.y; i < 32; i += 8)
        dst[(c0 + i) * C + o0 + tx] = t[tx][i];
}

// ---------------------------------------------------------------------------
// GEMM: out[v][o] = sum_c wt[c][o] * x[c][v] + b[o]
// Block tile 128 voxels x 128 channels, 256 threads, cp.async double-buffered.
// Thread tile: 8 voxels (as 4 packed f32x2 voxel-pairs) x 8 channels; FFMA2.
// ---------------------------------------------------------------------------
__global__ void __launch_bounds__(256, 2)
gemm_kernel(const float* __restrict__ x,
            const float* __restrict__ b0,
            const float* __restrict__ b1,
            const float* __restrict__ b2) {
    __shared__ __align__(16) float xs[2][16][128];
    __shared__ __align__(16) float ws[2][16][128];

    int mat = blockIdx.y;
    const float* wt   = g_wt + mat * C * C;
    const float* bias = (mat == 0) ? b0 : (mat == 1 ? b1 : b2);
    float* out = (mat == 0) ? g_q : (mat == 1 ? g_k : g_v);

    int tid = threadIdx.x;
    int tx = tid & 15, ty = tid >> 4;
    int v0 = blockIdx.x * 128;
    int ob = tx * 8;   // output-channel base
    int vb = ty * 8;   // voxel base

    // copy mapping: each thread copies rows r0, r0+8 at 16B column cl
    int r0 = tid >> 5;
    int cl = (tid & 31) * 4;

    u64 acc[4][8];
#pragma unroll
    for (int i = 0; i < 4; i++)
#pragma unroll
        for (int j = 0; j < 8; j++) acc[i][j] = 0ull;

    // prologue: chunk 0
    {
        cpa16(&xs[0][r0][cl],     x + r0 * NV + v0 + cl);
        cpa16(&xs[0][r0 + 8][cl], x + (r0 + 8) * NV + v0 + cl);
        cpa16(&ws[0][r0][cl],     wt + r0 * C + cl);
        cpa16(&ws[0][r0 + 8][cl], wt + (r0 + 8) * C + cl);
        cpcommit();
    }

    for (int ch = 0; ch < 8; ch++) {
        cpwait0();
        __syncthreads();
        if (ch < 7) {
            int cb = (ch + 1) * 16;
            int nb = (ch + 1) & 1;
            cpa16(&xs[nb][r0][cl],     x + (cb + r0) * NV + v0 + cl);
            cpa16(&xs[nb][r0 + 8][cl], x + (cb + r0 + 8) * NV + v0 + cl);
            cpa16(&ws[nb][r0][cl],     wt + (cb + r0) * C + cl);
            cpa16(&ws[nb][r0 + 8][cl], wt + (cb + r0 + 8) * C + cl);
            cpcommit();
        }
        const float (*xsb)[128] = xs[ch & 1];
        const float (*wsb)[128] = ws[ch & 1];

#pragma unroll
        for (int k = 0; k < 16; k++) {
            ulonglong2 xp0 = *(const ulonglong2*)&xsb[k][vb];
            ulonglong2 xp1 = *(const ulonglong2*)&xsb[k][vb + 4];
            float4 w0v = *(const float4*)&wsb[k][ob];
            float4 w1v = *(const float4*)&wsb[k][ob + 4];
            u64 xr[4] = {xp0.x, xp0.y, xp1.x, xp1.y};
            u64 wb[8];
            wb[0] = pk2(w0v.x, w0v.x); wb[1] = pk2(w0v.y, w0v.y);
            wb[2] = pk2(w0v.z, w0v.z); wb[3] = pk2(w0v.w, w0v.w);
            wb[4] = pk2(w1v.x, w1v.x); wb[5] = pk2(w1v.y, w1v.y);
            wb[6] = pk2(w1v.z, w1v.z); wb[7] = pk2(w1v.w, w1v.w);
#pragma unroll
            for (int i = 0; i < 4; i++)
#pragma unroll
                for (int j = 0; j < 8; j++)
                    fma2(acc[i][j], xr[i], wb[j]);
        }
    }

    float4 bb0 = *(const float4*)(bias + ob);
    float4 bb1 = *(const float4*)(bias + ob + 4);
#pragma unroll
    for (int i = 0; i < 4; i++) {
        float2 a[8];
#pragma unroll
        for (int j = 0; j < 8; j++) a[j] = up2(acc[i][j]);
        float* rlo = out + (v0 + vb + 2 * i)     * C + ob;
        float* rhi = out + (v0 + vb + 2 * i + 1) * C + ob;
        float4 lo0, lo1, hi0, hi1;
        lo0.x = a[0].x + bb0.x; lo0.y = a[1].x + bb0.y;
        lo0.z = a[2].x + bb0.z; lo0.w = a[3].x + bb0.w;
        lo1.x = a[4].x + bb1.x; lo1.y = a[5].x + bb1.y;
        lo1.z = a[6].x + bb1.z; lo1.w = a[7].x + bb1.w;
        hi0.x = a[0].y + bb0.x; hi0.y = a[1].y + bb0.y;
        hi0.z = a[2].y + bb0.z; hi0.w = a[3].y + bb0.w;
        hi1.x = a[4].y + bb1.x; hi1.y = a[5].y + bb1.y;
        hi1.z = a[6].y + bb1.z; hi1.w = a[7].y + bb1.w;
        *(float4*)rlo       = lo0;
        *(float4*)(rlo + 4) = lo1;
        *(float4*)rhi       = hi0;
        *(float4*)(rhi + 4) = hi1;
    }
}

// ---------------------------------------------------------------------------
// Attention: one WARP per voxel, 8 warps/block = 2x2x2 voxel cube.
// Neighbor offsets are compile-time constants folded into LDG immediates;
// in-bounds handled via a 27-bit mask. QK reduces use a 4-way folded
// butterfly (11 shuffles per 4 logits).
// ---------------------------------------------------------------------------
__global__ void __launch_bounds__(256)
attn_kernel(const float* __restrict__ bk,
            const float* __restrict__ bv,
            float* __restrict__ out) {
    const unsigned FULL = 0xffffffffu;
    int lane = threadIdx.x & 31;
    int wrp  = threadIdx.x >> 5;

    int t = blockIdx.x;                 // 0 .. 12^3-1
    int tH = t / 144;
    int rr = t - tH * 144;
    int tW = rr / 12;
    int tD = rr - tW * 12;
    int h = tH * 2 + ((wrp >> 2) & 1);
    int w = tW * 2 + ((wrp >> 1) & 1);
    int d = tD * 2 + (wrp & 1);
    int v = (h * S + w) * S + d;

    const float4 qv = *(const float4*)(g_q + v * C + lane * 4);

    // qsum over all 128 channels
    float qs = qv.x + qv.y + qv.z + qv.w;
#pragma unroll
    for (int o = 16; o; o >>= 1) qs += __shfl_xor_sync(FULL, qs, o);

    // 27-bit in-bounds mask (warp-uniform)
    bool h0 = h > 0, h2 = h < S - 1;
    bool w0 = w > 0, w2 = w < S - 1;
    bool d0 = d > 0, d2 = d < S - 1;
    unsigned m = 0;
#pragma unroll
    for (int s = 0; s < NW; s++) {
        int di = s / 9, dj = (s / 3) % 3, dl = s % 3;
        bool ok = (di == 0 ? h0 : (di == 2 ? h2 : true)) &&
                  (dj == 0 ? w0 : (dj == 2 ? w2 : true)) &&
                  (dl == 0 ? d0 : (dl == 2 ? d2 : true));
        m |= ok ? (1u << s) : 0u;
    }

    const float* kb  = g_k + (size_t)v * C + lane * 4;
    const float* bkl = bk + lane * 4;

    // QK: 27 dots in 7 groups of 4 with folded reduce
    float logit = 0.f;
#pragma unroll
    for (int g = 0; g < 7; g++) {
        float p[4];
#pragma unroll
        for (int r = 0; r < 4; r++) {
            int s = 4 * g + r;
            if (s < NW) {
                int off = (s / 9 - 1) * (S * S) + ((s / 3) % 3 - 1) * S + (s % 3 - 1);
                const float* kp = ((m >> s) & 1) ? (kb + off * C) : bkl;
                float4 kv = *(const float4*)kp;
                float pp = qv.x * kv.x;
                pp = fmaf(qv.y, kv.y, pp);
                pp = fmaf(qv.z, kv.z, pp);
                pp = fmaf(qv.w, kv.w, pp);
                p[r] = pp;
            } else {
                p[r] = 0.f;
            }
        }
        float a0 = p[0] + __shfl_xor_sync(FULL, p[0], 16);
        float a1 = p[1] + __shfl_xor_sync(FULL, p[1], 16);
        float a2 = p[2] + __shfl_xor_sync(FULL, p[2], 16);
        float a3 = p[3] + __shfl_xor_sync(FULL, p[3], 16);
        float b0 = (lane < 16) ? a0 : a1;
        float b1 = (lane < 16) ? a2 : a3;
        float c0 = b0 + __shfl_xor_sync(FULL, b0, 8);
        float c1 = b1 + __shfl_xor_sync(FULL, b1, 8);
        float tt = __shfl_xor_sync(FULL, c1, 8);
        float dd = (lane & 8) ? tt : c0;
        dd += __shfl_xor_sync(FULL, dd, 4);
        dd += __shfl_xor_sync(FULL, dd, 2);
        dd += __shfl_xor_sync(FULL, dd, 1);
        // lanes 0-7: s0, 8-15: s2, 16-23: s1, 24-31: s3
        int srcl = ((lane & 1) << 4) | ((lane & 2) << 2);
        float t2 = __shfl_sync(FULL, dd, srcl);
        if ((lane >> 2) == g) logit = t2;
    }

    // softmax over 27, in-warp
    float bias = 0.f;
    if (lane < NW) bias = g_bias[lane];
    float li = (lane < NW) ? fmaf(qs, bias, logit) : -INFINITY;
    float mx = li;
#pragma unroll
    for (int o = 16; o; o >>= 1) mx = fmaxf(mx, __shfl_xor_sync(FULL, mx, o));
    float p = (lane < NW) ? __expf(li - mx) : 0.f;
    float ssum = p;
#pragma unroll
    for (int o = 16; o; o >>= 1) ssum += __shfl_xor_sync(FULL, ssum, o);
    float prob = p / ssum;

    // AV: weighted sum of 27 V rows
    const float* vb  = g_v + (size_t)v * C + lane * 4;
    const float* bvl = bv + lane * 4;
    float4 acc = make_float4(0.f, 0.f, 0.f, 0.f);
#pragma unroll
    for (int s = 0; s < NW; s++) {
        int off = (s / 9 - 1) * (S * S) + ((s / 3) % 3 - 1) * S + (s % 3 - 1);
        float ps = __shfl_sync(FULL, prob, s);
        const float* vp = ((m >> s) & 1) ? (vb + off * C) : bvl;
        float4 vv = *(const float4*)vp;
        acc.x = fmaf(ps, vv.x, acc.x);
        acc.y = fmaf(ps, vv.y, acc.y);
        acc.z = fmaf(ps, vv.z, acc.z);
        acc.w = fmaf(ps, vv.w, acc.w);
    }
    *(float4*)(out + (size_t)v * C + lane * 4) = acc;
}

// ---------------------------------------------------------------------------
// Launch.  Inputs: x, wq, bq, wk, bk, wv, bv, rel_h, rel_w, rel_d
// ---------------------------------------------------------------------------
extern "C" void kernel_launch(void* const* d_in, const int* in_sizes, int n_in,
                              void* d_out, int out_size) {
    const float* x   = (const float*)d_in[0];
    const float* wq  = (const float*)d_in[1];
    const float* bq  = (const float*)d_in[2];
    const float* wk  = (const float*)d_in[3];
    const float* bk  = (const float*)d_in[4];
    const float* wv  = (const float*)d_in[5];
    const float* bv  = (const float*)d_in[6];
    const float* rh  = (const float*)d_in[7];
    const float* rw  = (const float*)d_in[8];
    const float* rd  = (const float*)d_in[9];
    float* out = (float*)d_out;

    prep_kernel<<<1, 288>>>(rh, rw, rd);

    dim3 tgrid(4, 4, 3);
    wt_kernel<<<tgrid, dim3(32, 8)>>>(wq, wk, wv);

    dim3 ggrid(NV / 128, 3);
    gemm_kernel<<<ggrid, 256>>>(x, bq, bk, bv);

    attn_kernel<<<(S / 2) * (S / 2) * (S / 2), 256>>>(bk, bv, out);
}